// round 1
// baseline (speedup 1.0000x reference)
#include <cuda_runtime.h>
#include <math.h>

// Problem constants (fixed by setup_inputs)
#define Bv    16384
#define Cv    576          // N_CH*SIZE*SIZE
#define INFv  2304         // 4*Cv
#define HIDv  256
#define OUTFv 1152         // 2*Cv
#define Tv    20

// Persistent scratch (device globals; no allocations allowed)
__device__ float g_inp[(size_t)Bv * INFv];   // [x | p | y | z] slices of Cv
__device__ float g_h1 [(size_t)Bv * HIDv];
__device__ float g_h2 [(size_t)Bv * HIDv];
__device__ float g_dev[(size_t)Bv * OUTFv];  // [u_raw | v_raw]
__device__ float g_res[Tv];                  // sum((pr-y)^2) per iter
__device__ float g_del[Tv];                  // sum((x_new-z)^2) per iter
__device__ float g_Q  [Tv];                  // sum(out^2) per iter
__device__ float g_alpha;

__device__ __forceinline__ float warp_sum(float v) {
    #pragma unroll
    for (int o = 16; o > 0; o >>= 1) v += __shfl_down_sync(0xffffffffu, v, o);
    return v;
}

// ---------------------------------------------------------------------------
// Init: pack x0 into all four state slices; zero accumulators.
// ---------------------------------------------------------------------------
__global__ void init_kernel(const float* __restrict__ noisy) {
    long i = blockIdx.x * (long)blockDim.x + threadIdx.x;
    if (i < Tv) { g_res[i] = 0.f; g_del[i] = 0.f; g_Q[i] = 0.f; }
    if (i == 0) g_alpha = 0.f;
    if (i < (long)Bv * Cv) {
        int b = (int)(i / Cv), c = (int)(i - (long)b * Cv);
        float v = (c < 64) ? noisy[b * 64 + c] : 0.f;
        float* row = g_inp + (size_t)b * INFv;
        row[c] = v; row[Cv + c] = v; row[2*Cv + c] = v; row[3*Cv + c] = v;
    }
}

// ---------------------------------------------------------------------------
// alpha(n) from previous iteration's delta and Q
// ---------------------------------------------------------------------------
__global__ void alpha_kernel(int n) {
    float delta  = g_del[n - 1];
    float Q      = 1.5f * g_Q[n - 1] + 1e-12f;
    float budget = 0.99f * fmaxf(delta, 0.f);
    g_alpha = sqrtf(fminf(budget / Q, 1.f));
}

// ---------------------------------------------------------------------------
// Elementwise step: in-place update of [x|p|y|z], folds u=alpha*u_raw,
// accumulates res^2 and delta reductions.
// ---------------------------------------------------------------------------
__global__ void step_kernel(int n) {
    __shared__ float sred[16];
    int i = blockIdx.x * blockDim.x + threadIdx.x;
    int b = i / Cv, c = i - b * Cv;
    float* row = g_inp + (size_t)b * INFv;
    float x = row[c], p = row[Cv + c], y = row[2*Cv + c], z = row[3*Cv + c];

    float u = 0.f, v = 0.f;
    if (n > 0) {
        float al = g_alpha;
        const float* orow = g_dev + (size_t)b * OUTFv;
        u = al * orow[c];
        v = al * orow[Cv + c];
    }
    float nf = (float)n;
    float a  = nf / (nf + 3.f);

    float yn = x + a * (y - x) + u;
    float zp = a * (z - p);
    float zn = x + a * (p - x) + zp + u + v;
    float zm = zn - yn;                               // z - gam*Cy, Cy=y, gam=1
    float pr = copysignf(fmaxf(fabsf(zm) - 0.1f, 0.f), zm);
    float xn = x + (pr - zn) + zp;

    row[c] = xn; row[Cv + c] = pr; row[2*Cv + c] = yn; row[3*Cv + c] = zn;

    float r = pr - yn; r *= r;
    float d = xn - zn; d *= d;
    r = warp_sum(r); d = warp_sum(d);
    int lane = threadIdx.x & 31, wid = threadIdx.x >> 5;
    if (lane == 0) { sred[wid] = r; sred[8 + wid] = d; }
    __syncthreads();
    if (wid == 0) {
        float rr = (lane < 8) ? sred[lane] : 0.f;
        rr = warp_sum(rr);
        if (lane == 0) atomicAdd(&g_res[n], rr);
    } else if (wid == 1) {
        float dd = (lane < 8) ? sred[8 + lane] : 0.f;
        dd = warp_sum(dd);
        if (lane == 0) atomicAdd(&g_del[n], dd);
    }
}

// ---------------------------------------------------------------------------
// SGEMM: C[M,N] = act(A[M,K] @ W[K,N] + bias), optional sum(C^2) accumulation.
// 128x128 tile, BK=16, 256 threads, 8x8 per-thread register tile.
// All dims are exact multiples (M=16384, N in {256,1152}, K in {2304,256}).
// ---------------------------------------------------------------------------
template<bool RELU, bool QSUM>
__global__ void __launch_bounds__(256)
gemm_kernel(const float* __restrict__ A, const float* __restrict__ W,
            const float* __restrict__ bias, float* __restrict__ C,
            int M, int N, int K, float* __restrict__ Qacc)
{
    __shared__ float As[16][128];
    __shared__ float Bs[16][128];
    const int m0 = blockIdx.y * 128;
    const int n0 = blockIdx.x * 128;
    const int tid = threadIdx.x;
    const int tx = tid & 15;   // n-dir
    const int ty = tid >> 4;   // m-dir

    float acc[8][8];
    #pragma unroll
    for (int i = 0; i < 8; ++i)
        #pragma unroll
        for (int j = 0; j < 8; ++j) acc[i][j] = 0.f;

    for (int k0 = 0; k0 < K; k0 += 16) {
        #pragma unroll
        for (int l = 0; l < 2; ++l) {
            int idx = tid + l * 256;                 // 0..511
            int arow = idx >> 2, avec = idx & 3;     // A tile 128x16
            float4 va = *(const float4*)(A + (size_t)(m0 + arow) * K + k0 + avec * 4);
            As[avec * 4 + 0][arow] = va.x;
            As[avec * 4 + 1][arow] = va.y;
            As[avec * 4 + 2][arow] = va.z;
            As[avec * 4 + 3][arow] = va.w;
            int brow = idx >> 5, bvec = idx & 31;    // W tile 16x128
            float4 vb = *(const float4*)(W + (size_t)(k0 + brow) * N + n0 + bvec * 4);
            *(float4*)(&Bs[brow][bvec * 4]) = vb;
        }
        __syncthreads();
        #pragma unroll
        for (int k = 0; k < 16; ++k) {
            float ar[8], br[8];
            *(float4*)(ar)     = *(const float4*)(&As[k][ty * 8]);
            *(float4*)(ar + 4) = *(const float4*)(&As[k][ty * 8 + 4]);
            *(float4*)(br)     = *(const float4*)(&Bs[k][tx * 8]);
            *(float4*)(br + 4) = *(const float4*)(&Bs[k][tx * 8 + 4]);
            #pragma unroll
            for (int i = 0; i < 8; ++i)
                #pragma unroll
                for (int j = 0; j < 8; ++j)
                    acc[i][j] += ar[i] * br[j];
        }
        __syncthreads();
    }

    float bb[8];
    *(float4*)(bb)     = *(const float4*)(bias + n0 + tx * 8);
    *(float4*)(bb + 4) = *(const float4*)(bias + n0 + tx * 8 + 4);

    float qs = 0.f;
    #pragma unroll
    for (int i = 0; i < 8; ++i) {
        int m = m0 + ty * 8 + i;
        #pragma unroll
        for (int j = 0; j < 8; ++j) {
            float cvl = acc[i][j] + bb[j];
            if (RELU) cvl = fmaxf(cvl, 0.f);
            if (QSUM) qs += cvl * cvl;
            acc[i][j] = cvl;
        }
        *(float4*)(C + (size_t)m * N + n0 + tx * 8)     =
            make_float4(acc[i][0], acc[i][1], acc[i][2], acc[i][3]);
        *(float4*)(C + (size_t)m * N + n0 + tx * 8 + 4) =
            make_float4(acc[i][4], acc[i][5], acc[i][6], acc[i][7]);
    }

    if (QSUM) {
        __shared__ float sq[8];
        qs = warp_sum(qs);
        int lane = tid & 31, wid = tid >> 5;
        if (lane == 0) sq[wid] = qs;
        __syncthreads();
        if (tid < 32) {
            float t = (tid < 8) ? sq[tid] : 0.f;
            t = warp_sum(t);
            if (tid == 0) atomicAdd(Qacc, t);
        }
    }
}

// ---------------------------------------------------------------------------
// Finalize: p slice -> out[0 : B*C), residuals -> out[B*C : B*C + T)
// ---------------------------------------------------------------------------
__global__ void finalize_kernel(float* __restrict__ out) {
    long i = blockIdx.x * (long)blockDim.x + threadIdx.x;
    if (i < (long)Bv * Cv) {
        int b = (int)(i / Cv), c = (int)(i - (long)b * Cv);
        out[i] = g_inp[(size_t)b * INFv + Cv + c];
    }
    if (i < Tv) out[(long)Bv * Cv + i] = sqrtf(g_res[i] + 1e-12f);
}

// ---------------------------------------------------------------------------
extern "C" void kernel_launch(void* const* d_in, const int* in_sizes, int n_in,
                              void* d_out, int out_size) {
    const float* noisy = (const float*)d_in[0];
    const float* W1 = (const float*)d_in[1];
    const float* b1 = (const float*)d_in[2];
    const float* W2 = (const float*)d_in[3];
    const float* b2 = (const float*)d_in[4];
    const float* W3 = (const float*)d_in[5];
    const float* b3 = (const float*)d_in[6];
    float* out = (float*)d_out;

    float *inp, *h1, *h2, *dev, *Qarr;
    cudaGetSymbolAddress((void**)&inp,  g_inp);
    cudaGetSymbolAddress((void**)&h1,   g_h1);
    cudaGetSymbolAddress((void**)&h2,   g_h2);
    cudaGetSymbolAddress((void**)&dev,  g_dev);
    cudaGetSymbolAddress((void**)&Qarr, g_Q);

    const int NBLK = (Bv * Cv) / 256;   // 36864
    init_kernel<<<NBLK, 256>>>(noisy);

    dim3 g1(HIDv  / 128, Bv / 128);     // (2, 128)
    dim3 g2(HIDv  / 128, Bv / 128);     // (2, 128)
    dim3 g3(OUTFv / 128, Bv / 128);     // (9, 128)

    for (int n = 0; n < Tv; ++n) {
        if (n > 0) alpha_kernel<<<1, 1>>>(n);
        step_kernel<<<NBLK, 256>>>(n);
        gemm_kernel<true,  false><<<g1, 256>>>(inp, W1, b1, h1, Bv, HIDv,  INFv, nullptr);
        gemm_kernel<true,  false><<<g2, 256>>>(h1,  W2, b2, h2, Bv, HIDv,  HIDv, nullptr);
        gemm_kernel<false, true ><<<g3, 256>>>(h2,  W3, b3, dev, Bv, OUTFv, HIDv, Qarr + n);
    }
    finalize_kernel<<<NBLK, 256>>>(out);
}

// round 3
// speedup vs baseline: 2.9349x; 2.9349x over previous
#include <cuda_runtime.h>
#include <cuda.h>
#include <math.h>
#include <stdint.h>

// Problem constants (fixed by setup_inputs)
#define Bv    16384
#define Cv    576          // N_CH*SIZE*SIZE
#define INFv  2304         // 4*Cv
#define HIDv  256
#define OUTFv 1152         // 2*Cv
#define Tv    20

// Persistent scratch (device globals; no allocations allowed)
__device__ __align__(1024) float g_inp[(size_t)Bv * INFv];   // [x | p | y | z]
__device__ __align__(1024) float g_h1 [(size_t)Bv * HIDv];
__device__ __align__(1024) float g_h2 [(size_t)Bv * HIDv];
__device__ __align__(1024) float g_dev[(size_t)Bv * OUTFv];  // [u_raw | v_raw]
__device__ __align__(1024) float g_W1t[(size_t)HIDv  * INFv]; // [256,2304]
__device__ __align__(1024) float g_W2t[(size_t)HIDv  * HIDv]; // [256,256]
__device__ __align__(1024) float g_W3t[(size_t)OUTFv * HIDv]; // [1152,256]
__device__ float g_res[Tv];
__device__ float g_del[Tv];
__device__ float g_Q  [Tv];
__device__ float g_alpha;

// ---------------------------------------------------------------------------
// PTX helpers
// ---------------------------------------------------------------------------
__device__ __forceinline__ uint32_t smem_to_u32(const void* p) {
    uint32_t a;
    asm("{ .reg .u64 t; cvta.to.shared.u64 t, %1; cvt.u32.u64 %0, t; }"
        : "=r"(a) : "l"(p));
    return a;
}

#define MBARRIER_INIT(addr, cnt) \
    asm volatile("mbarrier.init.shared.b64 [%0], %1;" :: "r"((uint32_t)(addr)), "r"((uint32_t)(cnt)) : "memory")
#define MBARRIER_EXPECT_TX(addr, bytes) \
    asm volatile("mbarrier.arrive.expect_tx.shared.b64 _, [%0], %1;" :: "r"((uint32_t)(addr)), "r"((uint32_t)(bytes)) : "memory")

#define MBARRIER_WAIT_PARITY(mbar, par) do { \
    uint32_t _m = (uint32_t)(mbar), _p = (uint32_t)(par), _d; \
    asm volatile("{\n\t.reg .pred p;\n\t" \
        "mbarrier.try_wait.parity.acquire.cta.shared::cta.b64 p, [%1], %2;\n\t" \
        "selp.b32 %0, 1, 0, p;\n\t}" : "=r"(_d) : "r"(_m), "r"(_p) : "memory"); \
    if (!_d) { \
        asm volatile("{\n\t.reg .pred P1;\n\t" \
            "W_%=:\n\t" \
            "mbarrier.try_wait.parity.acquire.cta.shared::cta.b64 P1, [%0], %1, 0x989680;\n\t" \
            "@P1 bra.uni D_%=;\n\tbra.uni W_%=;\n\tD_%=:\n\t}" \
            :: "r"(_m), "r"(_p) : "memory"); \
    } \
} while(0)

#define TMA_LOAD_2D(smem_addr, map_ptr, cx, cy, mbar) \
    asm volatile("cp.async.bulk.tensor.2d.shared::cta.global.tile.mbarrier::complete_tx::bytes " \
        "[%0], [%1, {%2, %3}], [%4];" \
        :: "r"((uint32_t)(smem_addr)), "l"(map_ptr), "r"((int32_t)(cx)), "r"((int32_t)(cy)), \
           "r"((uint32_t)(mbar)) : "memory")

#define FENCE_PROXY_ASYNC() asm volatile("fence.proxy.async.shared::cta;" ::: "memory")

__device__ __forceinline__ uint32_t f2tf(float v) {
    uint32_t u;
    asm("cvt.rna.tf32.f32 %0, %1;" : "=r"(u) : "f"(v));
    return u;
}

__device__ __forceinline__ void mma_tf32(float* d, const uint32_t* a,
                                         uint32_t b0, uint32_t b1) {
    asm volatile(
        "mma.sync.aligned.m16n8k8.row.col.f32.tf32.tf32.f32 "
        "{%0,%1,%2,%3}, {%4,%5,%6,%7}, {%8,%9}, {%0,%1,%2,%3};"
        : "+f"(d[0]), "+f"(d[1]), "+f"(d[2]), "+f"(d[3])
        : "r"(a[0]), "r"(a[1]), "r"(a[2]), "r"(a[3]), "r"(b0), "r"(b1));
}

__device__ __forceinline__ float warp_sum(float v) {
    #pragma unroll
    for (int o = 16; o > 0; o >>= 1) v += __shfl_down_sync(0xffffffffu, v, o);
    return v;
}

// SW128-swizzled index of element (row, k) in a [rows][32-float] tile
__device__ __forceinline__ int swz(int row, int k) {
    return row * 32 + ((((k) >> 2) ^ (row & 7)) << 2) + ((k) & 3);
}

// ---------------------------------------------------------------------------
// tf32 mma.sync GEMM: C[M, Nglob] = act(A[M,K] @ Wt[Nglob,K]^T + bias)
// CTA tile: 128 x (NT_WARP*32). 512 threads = 16 warps (4m x 4n).
// Warp tile: 32 x (NT_WARP*8). TMA SW128 loads, multi-stage mbarrier pipeline.
// ---------------------------------------------------------------------------
template<int NT_WARP, int STAGES, bool RELU, bool QSUM>
__global__ void __launch_bounds__(512, 1)
mma_gemm(const __grid_constant__ CUtensorMap tmA,
         const __grid_constant__ CUtensorMap tmB,
         const float* __restrict__ bias, float* __restrict__ C,
         int Nglob, int K, float* __restrict__ Qacc)
{
    constexpr int N_TILE  = NT_WARP * 32;         // 256 or 128
    constexpr int NB      = N_TILE / 128;         // B TMA loads per stage
    constexpr int A_BYTES = 128 * 32 * 4;         // 16KB
    constexpr int B_BYTES = N_TILE * 32 * 4;      // 32KB or 16KB
    constexpr int STAGE_B = A_BYTES + B_BYTES;

    extern __shared__ char smem[];
    const uint32_t sb = smem_to_u32(smem);
    const int tid  = threadIdx.x;
    const int wid  = tid >> 5;
    const int lane = tid & 31;
    const int warp_m = wid >> 2;                  // 0..3
    const int warp_n = wid & 3;                   // 0..3
    const int m0 = blockIdx.y * 128;
    const int n0 = blockIdx.x * N_TILE;
    const int niter = K / 32;

    const uint32_t FULLB    = sb;                 // STAGES * 8 bytes
    const uint32_t TILE     = sb + 1024;

    if (tid == 0) {
        #pragma unroll
        for (int s = 0; s < STAGES; ++s) MBARRIER_INIT(FULLB + s * 8, 1);
        FENCE_PROXY_ASYNC();
    }
    __syncthreads();

    // Prologue: fill STAGES-1 slots
    if (tid == 0) {
        #pragma unroll
        for (int s = 0; s < STAGES - 1; ++s) {
            if (s < niter) {
                MBARRIER_EXPECT_TX(FULLB + s * 8, STAGE_B);
                TMA_LOAD_2D(TILE + s * STAGE_B, &tmA, s * 32, m0, FULLB + s * 8);
                #pragma unroll
                for (int j = 0; j < NB; ++j)
                    TMA_LOAD_2D(TILE + s * STAGE_B + A_BYTES + j * 16384, &tmB,
                                s * 32, n0 + j * 128, FULLB + s * 8);
            }
        }
    }

    float acc[2][NT_WARP][4];
    #pragma unroll
    for (int mt = 0; mt < 2; ++mt)
        #pragma unroll
        for (int nt = 0; nt < NT_WARP; ++nt)
            #pragma unroll
            for (int q = 0; q < 4; ++q) acc[mt][nt][q] = 0.f;

    const int r_lo = lane >> 2;   // 0..7
    const int c_lo = lane & 3;    // 0..3

    for (int it = 0; it < niter; ++it) {
        const int s = it % STAGES;
        MBARRIER_WAIT_PARITY(FULLB + s * 8, (it / STAGES) & 1);

        // issue load for it+STAGES-1 (its slot was consumed at it-1)
        if (tid == 0) {
            int nx = it + STAGES - 1;
            if (nx < niter) {
                int sx = nx % STAGES;
                MBARRIER_EXPECT_TX(FULLB + sx * 8, STAGE_B);
                TMA_LOAD_2D(TILE + sx * STAGE_B, &tmA, nx * 32, m0, FULLB + sx * 8);
                #pragma unroll
                for (int j = 0; j < NB; ++j)
                    TMA_LOAD_2D(TILE + sx * STAGE_B + A_BYTES + j * 16384, &tmB,
                                nx * 32, n0 + j * 128, FULLB + sx * 8);
            }
        }

        const float* As = (const float*)(smem + 1024 + s * STAGE_B);
        const float* Bs = As + A_BYTES / 4;

        #pragma unroll
        for (int ks = 0; ks < 4; ++ks) {
            const int g0 = 2 * ks;   // (k0>>2)
            uint32_t af[2][4];
            #pragma unroll
            for (int mt = 0; mt < 2; ++mt) {
                int rm = warp_m * 32 + mt * 16;
                int r0 = rm + r_lo, r1 = r0 + 8;
                af[mt][0] = f2tf(As[r0 * 32 + (((g0    ) ^ (r0 & 7)) << 2) + c_lo]);
                af[mt][1] = f2tf(As[r1 * 32 + (((g0    ) ^ (r1 & 7)) << 2) + c_lo]);
                af[mt][2] = f2tf(As[r0 * 32 + (((g0 + 1) ^ (r0 & 7)) << 2) + c_lo]);
                af[mt][3] = f2tf(As[r1 * 32 + (((g0 + 1) ^ (r1 & 7)) << 2) + c_lo]);
            }
            #pragma unroll
            for (int nt = 0; nt < NT_WARP; ++nt) {
                int rn = warp_n * NT_WARP * 8 + nt * 8 + r_lo;
                uint32_t b0 = f2tf(Bs[rn * 32 + (((g0    ) ^ (rn & 7)) << 2) + c_lo]);
                uint32_t b1 = f2tf(Bs[rn * 32 + (((g0 + 1) ^ (rn & 7)) << 2) + c_lo]);
                mma_tf32(acc[0][nt], af[0], b0, b1);
                mma_tf32(acc[1][nt], af[1], b0, b1);
            }
        }
        __syncthreads();
    }

    // Epilogue: bias + activation (+ Qsum), direct float2 stores
    float qs = 0.f;
    const int nw = n0 + warp_n * NT_WARP * 8;
    #pragma unroll
    for (int nt = 0; nt < NT_WARP; ++nt) {
        const int col = nw + nt * 8 + c_lo * 2;
        const float bias0 = bias[col], bias1 = bias[col + 1];
        #pragma unroll
        for (int mt = 0; mt < 2; ++mt) {
            const int row0 = m0 + warp_m * 32 + mt * 16 + r_lo;
            float v0 = acc[mt][nt][0] + bias0;
            float v1 = acc[mt][nt][1] + bias1;
            float v2 = acc[mt][nt][2] + bias0;
            float v3 = acc[mt][nt][3] + bias1;
            if (RELU) {
                v0 = fmaxf(v0, 0.f); v1 = fmaxf(v1, 0.f);
                v2 = fmaxf(v2, 0.f); v3 = fmaxf(v3, 0.f);
            }
            if (QSUM) qs += v0 * v0 + v1 * v1 + v2 * v2 + v3 * v3;
            *(float2*)(C + (size_t)row0 * Nglob + col)       = make_float2(v0, v1);
            *(float2*)(C + (size_t)(row0 + 8) * Nglob + col) = make_float2(v2, v3);
        }
    }
    if (QSUM) {
        qs = warp_sum(qs);
        if (lane == 0) atomicAdd(Qacc, qs);
    }
}

// ---------------------------------------------------------------------------
// Weight transpose: Wt[n*K + k] = W[k*N + n]
// ---------------------------------------------------------------------------
__global__ void transpose_kernel(const float* __restrict__ W, float* __restrict__ Wt,
                                 int K, int N)
{
    __shared__ float t[32][33];
    int k0 = blockIdx.x * 32, n0 = blockIdx.y * 32;
    int x = threadIdx.x, y0 = threadIdx.y;
    #pragma unroll
    for (int dy = 0; dy < 32; dy += 8) {
        int k = k0 + y0 + dy, n = n0 + x;
        if (k < K && n < N) t[y0 + dy][x] = W[(size_t)k * N + n];
    }
    __syncthreads();
    #pragma unroll
    for (int dy = 0; dy < 32; dy += 8) {
        int n = n0 + y0 + dy, k = k0 + x;
        if (n < N && k < K) Wt[(size_t)n * K + k] = t[x][y0 + dy];
    }
}

// ---------------------------------------------------------------------------
// Init / alpha / step / finalize
// ---------------------------------------------------------------------------
__global__ void init_kernel(const float* __restrict__ noisy) {
    long i = blockIdx.x * (long)blockDim.x + threadIdx.x;
    if (i < Tv) { g_res[i] = 0.f; g_del[i] = 0.f; g_Q[i] = 0.f; }
    if (i == 0) g_alpha = 0.f;
    if (i < (long)Bv * Cv) {
        int b = (int)(i / Cv), c = (int)(i - (long)b * Cv);
        float v = (c < 64) ? noisy[b * 64 + c] : 0.f;
        float* row = g_inp + (size_t)b * INFv;
        row[c] = v; row[Cv + c] = v; row[2*Cv + c] = v; row[3*Cv + c] = v;
    }
}

__global__ void alpha_kernel(int n) {
    float delta  = g_del[n - 1];
    float Q      = 1.5f * g_Q[n - 1] + 1e-12f;
    float budget = 0.99f * fmaxf(delta, 0.f);
    g_alpha = sqrtf(fminf(budget / Q, 1.f));
}

__global__ void step_kernel(int n) {
    __shared__ float sred[16];
    int i = blockIdx.x * blockDim.x + threadIdx.x;
    int b = i / Cv, c = i - b * Cv;
    float* row = g_inp + (size_t)b * INFv;
    float x = row[c], p = row[Cv + c], y = row[2*Cv + c], z = row[3*Cv + c];

    float u = 0.f, v = 0.f;
    if (n > 0) {
        float al = g_alpha;
        const float* orow = g_dev + (size_t)b * OUTFv;
        u = al * orow[c];
        v = al * orow[Cv + c];
    }
    float nf = (float)n;
    float a  = nf / (nf + 3.f);

    float yn = x + a * (y - x) + u;
    float zp = a * (z - p);
    float zn = x + a * (p - x) + zp + u + v;
    float zm = zn - yn;
    float pr = copysignf(fmaxf(fabsf(zm) - 0.1f, 0.f), zm);
    float xn = x + (pr - zn) + zp;

    row[c] = xn; row[Cv + c] = pr; row[2*Cv + c] = yn; row[3*Cv + c] = zn;

    float r = pr - yn; r *= r;
    float d = xn - zn; d *= d;
    r = warp_sum(r); d = warp_sum(d);
    int lane = threadIdx.x & 31, wid = threadIdx.x >> 5;
    if (lane == 0) { sred[wid] = r; sred[8 + wid] = d; }
    __syncthreads();
    if (wid == 0) {
        float rr = (lane < 8) ? sred[lane] : 0.f;
        rr = warp_sum(rr);
        if (lane == 0) atomicAdd(&g_res[n], rr);
    } else if (wid == 1) {
        float dd = (lane < 8) ? sred[8 + lane] : 0.f;
        dd = warp_sum(dd);
        if (lane == 0) atomicAdd(&g_del[n], dd);
    }
}

__global__ void finalize_kernel(float* __restrict__ out) {
    long i = blockIdx.x * (long)blockDim.x + threadIdx.x;
    if (i < (long)Bv * Cv) {
        int b = (int)(i / Cv), c = (int)(i - (long)b * Cv);
        out[i] = g_inp[(size_t)b * INFv + Cv + c];
    }
    if (i < Tv) out[(long)Bv * Cv + i] = sqrtf(g_res[i] + 1e-12f);
}

// ---------------------------------------------------------------------------
// Host side
// ---------------------------------------------------------------------------
typedef CUresult (*EncodeFn)(CUtensorMap*, CUtensorMapDataType, cuuint32_t, void*,
                             const cuuint64_t*, const cuuint64_t*, const cuuint32_t*,
                             const cuuint32_t*, CUtensorMapInterleave, CUtensorMapSwizzle,
                             CUtensorMapL2promotion, CUtensorMapFloatOOBfill);

static void make_map(EncodeFn enc, CUtensorMap* tm, void* base, int Kdim, int rows) {
    cuuint64_t dims[2]    = {(cuuint64_t)Kdim, (cuuint64_t)rows};
    cuuint64_t strides[1] = {(cuuint64_t)Kdim * 4};
    cuuint32_t box[2]     = {32u, 128u};
    cuuint32_t es[2]      = {1u, 1u};
    enc(tm, CU_TENSOR_MAP_DATA_TYPE_FLOAT32, 2, base, dims, strides, box, es,
        CU_TENSOR_MAP_INTERLEAVE_NONE, CU_TENSOR_MAP_SWIZZLE_128B,
        CU_TENSOR_MAP_L2_PROMOTION_L2_128B, CU_TENSOR_MAP_FLOAT_OOB_FILL_NONE);
}

extern "C" void kernel_launch(void* const* d_in, const int* in_sizes, int n_in,
                              void* d_out, int out_size) {
    const float* noisy = (const float*)d_in[0];
    const float* W1 = (const float*)d_in[1];
    const float* b1 = (const float*)d_in[2];
    const float* W2 = (const float*)d_in[3];
    const float* b2 = (const float*)d_in[4];
    const float* W3 = (const float*)d_in[5];
    const float* b3 = (const float*)d_in[6];
    float* out = (float*)d_out;

    float *inp, *h1, *h2, *dev, *Qarr, *W1t, *W2t, *W3t;
    cudaGetSymbolAddress((void**)&inp,  g_inp);
    cudaGetSymbolAddress((void**)&h1,   g_h1);
    cudaGetSymbolAddress((void**)&h2,   g_h2);
    cudaGetSymbolAddress((void**)&dev,  g_dev);
    cudaGetSymbolAddress((void**)&Qarr, g_Q);
    cudaGetSymbolAddress((void**)&W1t,  g_W1t);
    cudaGetSymbolAddress((void**)&W2t,  g_W2t);
    cudaGetSymbolAddress((void**)&W3t,  g_W3t);

    static EncodeFn enc = nullptr;
    if (!enc) {
        void* p = nullptr;
        cudaDriverEntryPointQueryResult st;
        cudaGetDriverEntryPoint("cuTensorMapEncodeTiled", &p, cudaEnableDefault, &st);
        enc = (EncodeFn)p;
    }

    CUtensorMap tA1, tB1, tA2, tB2, tA3, tB3;
    make_map(enc, &tA1, inp, INFv, Bv);
    make_map(enc, &tB1, W1t, INFv, HIDv);
    make_map(enc, &tA2, h1,  HIDv, Bv);
    make_map(enc, &tB2, W2t, HIDv, HIDv);
    make_map(enc, &tA3, h2,  HIDv, Bv);
    make_map(enc, &tB3, W3t, HIDv, OUTFv);

    // smem: NT_WARP=8 -> stage 48KB, 3 stages; NT_WARP=4 -> stage 32KB, 4 stages
    const int SMEM_WIDE = 1024 + 3 * (16384 + 32768);   // 148480
    const int SMEM_NARW = 1024 + 4 * (16384 + 16384);   // 132096
    static bool attr_set = false;
    if (!attr_set) {
        cudaFuncSetAttribute(mma_gemm<8,3,true ,false>, cudaFuncAttributeMaxDynamicSharedMemorySize, SMEM_WIDE);
        cudaFuncSetAttribute(mma_gemm<4,4,false,true >, cudaFuncAttributeMaxDynamicSharedMemorySize, SMEM_NARW);
        attr_set = true;
    }

    dim3 tb(32, 8);
    transpose_kernel<<<dim3(INFv/32, HIDv/32),  tb>>>(W1, W1t, INFv, HIDv);
    transpose_kernel<<<dim3(HIDv/32, HIDv/32),  tb>>>(W2, W2t, HIDv, HIDv);
    transpose_kernel<<<dim3(HIDv/32, OUTFv/32), tb>>>(W3, W3t, HIDv, OUTFv);

    const int NBLK = (Bv * Cv) / 256;
    init_kernel<<<NBLK, 256>>>(noisy);

    dim3 g12(1, Bv / 128);          // N=256 in one CTA column
    dim3 g3 (OUTFv / 128, Bv / 128); // (9, 128)

    for (int n = 0; n < Tv; ++n) {
        if (n > 0) alpha_kernel<<<1, 1>>>(n);
        step_kernel<<<NBLK, 256>>>(n);
        mma_gemm<8,3,true ,false><<<g12, 512, SMEM_WIDE>>>(tA1, tB1, b1, h1,  HIDv,  INFv, nullptr);
        mma_gemm<8,3,true ,false><<<g12, 512, SMEM_WIDE>>>(tA2, tB2, b2, h2,  HIDv,  HIDv, nullptr);
        mma_gemm<4,4,false,true ><<<g3,  512, SMEM_NARW>>>(tA3, tB3, b3, dev, OUTFv, HIDv, Qarr + n);
    }
    finalize_kernel<<<NBLK, 256>>>(out);
}

// round 4
// speedup vs baseline: 4.3186x; 1.4715x over previous
#include <cuda_runtime.h>
#include <cuda.h>
#include <cuda_fp16.h>
#include <math.h>
#include <stdint.h>

// Problem constants (fixed by setup_inputs)
#define Bv    16384
#define Cv    576          // N_CH*SIZE*SIZE
#define INFv  2304         // 4*Cv
#define HIDv  256
#define OUTFv 1152         // 2*Cv
#define Tv    20

// Persistent scratch (device globals; no allocations allowed)
__device__ __align__(1024) float  g_inp [(size_t)Bv * INFv];   // fp32 state [x|p|y|z]
__device__ __align__(1024) __half g_inph[(size_t)Bv * INFv];   // fp16 state copy (GEMM1 A)
__device__ __align__(1024) __half g_h1h [(size_t)Bv * HIDv];
__device__ __align__(1024) __half g_h2h [(size_t)Bv * HIDv];
__device__ __align__(1024) __half g_devh[(size_t)Bv * OUTFv];  // [u_raw | v_raw] fp16
__device__ __align__(1024) __half g_W1h[(size_t)HIDv  * INFv]; // K-major [256,2304]
__device__ __align__(1024) __half g_W2h[(size_t)HIDv  * HIDv];
__device__ __align__(1024) __half g_W3h[(size_t)OUTFv * HIDv];
__device__ float g_res[Tv];
__device__ float g_del[Tv];
__device__ float g_Q  [Tv];

// ---------------------------------------------------------------------------
// PTX helpers
// ---------------------------------------------------------------------------
__device__ __forceinline__ uint32_t smem_to_u32(const void* p) {
    uint32_t a;
    asm("{ .reg .u64 t; cvta.to.shared.u64 t, %1; cvt.u32.u64 %0, t; }"
        : "=r"(a) : "l"(p));
    return a;
}

#define MBARRIER_INIT(addr, cnt) \
    asm volatile("mbarrier.init.shared.b64 [%0], %1;" :: "r"((uint32_t)(addr)), "r"((uint32_t)(cnt)) : "memory")
#define MBARRIER_EXPECT_TX(addr, bytes) \
    asm volatile("mbarrier.arrive.expect_tx.shared.b64 _, [%0], %1;" :: "r"((uint32_t)(addr)), "r"((uint32_t)(bytes)) : "memory")

#define MBARRIER_WAIT_PARITY(mbar, par) do { \
    uint32_t _m = (uint32_t)(mbar), _p = (uint32_t)(par), _d; \
    asm volatile("{\n\t.reg .pred p;\n\t" \
        "mbarrier.try_wait.parity.acquire.cta.shared::cta.b64 p, [%1], %2;\n\t" \
        "selp.b32 %0, 1, 0, p;\n\t}" : "=r"(_d) : "r"(_m), "r"(_p) : "memory"); \
    if (!_d) { \
        asm volatile("{\n\t.reg .pred P1;\n\t" \
            "W_%=:\n\t" \
            "mbarrier.try_wait.parity.acquire.cta.shared::cta.b64 P1, [%0], %1, 0x989680;\n\t" \
            "@P1 bra.uni D_%=;\n\tbra.uni W_%=;\n\tD_%=:\n\t}" \
            :: "r"(_m), "r"(_p) : "memory"); \
    } \
} while(0)

#define TMA_LOAD_2D(smem_addr, map_ptr, cx, cy, mbar) \
    asm volatile("cp.async.bulk.tensor.2d.shared::cta.global.tile.mbarrier::complete_tx::bytes " \
        "[%0], [%1, {%2, %3}], [%4];" \
        :: "r"((uint32_t)(smem_addr)), "l"(map_ptr), "r"((int32_t)(cx)), "r"((int32_t)(cy)), \
           "r"((uint32_t)(mbar)) : "memory")

#define FENCE_PROXY_ASYNC() asm volatile("fence.proxy.async.shared::cta;" ::: "memory")

#define LDMATRIX_X4(r0, r1, r2, r3, addr) \
    asm volatile("ldmatrix.sync.aligned.m8n8.x4.shared.b16 {%0,%1,%2,%3}, [%4];" \
        : "=r"(r0), "=r"(r1), "=r"(r2), "=r"(r3) : "r"(addr))

__device__ __forceinline__ void mma_f16(float* d, const uint32_t* a,
                                        uint32_t b0, uint32_t b1) {
    asm volatile(
        "mma.sync.aligned.m16n8k16.row.col.f32.f16.f16.f32 "
        "{%0,%1,%2,%3}, {%4,%5,%6,%7}, {%8,%9}, {%0,%1,%2,%3};"
        : "+f"(d[0]), "+f"(d[1]), "+f"(d[2]), "+f"(d[3])
        : "r"(a[0]), "r"(a[1]), "r"(a[2]), "r"(a[3]), "r"(b0), "r"(b1));
}

__device__ __forceinline__ float warp_sum(float v) {
    #pragma unroll
    for (int o = 16; o > 0; o >>= 1) v += __shfl_down_sync(0xffffffffu, v, o);
    return v;
}

// ---------------------------------------------------------------------------
// fp16 mma.sync GEMM: C[M, Nglob] = act(A[M,K] @ Wt[Nglob,K]^T + bias)
// CTA tile: (MT*64) x (NT*32). 512 threads = 16 warps (4m x 4n).
// Warp tile: (MT*16) x (NT*8). TMA SW128 fp16 tiles (128 rows x 64 halves),
// K-stage = 64, ldmatrix.x4 fragment loads, STAGES-deep mbarrier pipeline.
// ---------------------------------------------------------------------------
template<int MT, int NT, int STAGES, bool RELU, bool QSUM>
__global__ void __launch_bounds__(512, 1)
hgemm(const __grid_constant__ CUtensorMap tmA,
      const __grid_constant__ CUtensorMap tmB,
      const float* __restrict__ bias, __half* __restrict__ C,
      int Nglob, int K, float* __restrict__ Qacc)
{
    constexpr int CTA_M   = MT * 64;
    constexpr int CTA_N   = NT * 32;
    constexpr int NA      = CTA_M / 128;      // A boxes per stage
    constexpr int NB      = CTA_N / 128;      // B boxes per stage
    constexpr int A_BYTES = CTA_M * 64 * 2;   // NA * 16KB
    constexpr int B_BYTES = CTA_N * 64 * 2;   // NB * 16KB
    constexpr int STAGE_B = A_BYTES + B_BYTES;

    extern __shared__ char smem[];
    const uint32_t sb = smem_to_u32(smem);
    const int tid  = threadIdx.x;
    const int wid  = tid >> 5;
    const int lane = tid & 31;
    const int warp_m = wid >> 2;
    const int warp_n = wid & 3;
    const int m0 = blockIdx.y * CTA_M;
    const int n0 = blockIdx.x * CTA_N;
    const int niter = K / 64;

    const uint32_t FULLB = sb;
    const uint32_t TILE  = sb + 1024;

    if (tid == 0) {
        #pragma unroll
        for (int s = 0; s < STAGES; ++s) MBARRIER_INIT(FULLB + s * 8, 1);
        FENCE_PROXY_ASYNC();
    }
    __syncthreads();

    if (tid == 0) {
        #pragma unroll
        for (int s = 0; s < STAGES - 1; ++s) {
            if (s < niter) {
                MBARRIER_EXPECT_TX(FULLB + s * 8, STAGE_B);
                #pragma unroll
                for (int j = 0; j < NA; ++j)
                    TMA_LOAD_2D(TILE + s * STAGE_B + j * 16384, &tmA,
                                s * 64, m0 + j * 128, FULLB + s * 8);
                #pragma unroll
                for (int j = 0; j < NB; ++j)
                    TMA_LOAD_2D(TILE + s * STAGE_B + A_BYTES + j * 16384, &tmB,
                                s * 64, n0 + j * 128, FULLB + s * 8);
            }
        }
    }

    float acc[MT][NT][4];
    #pragma unroll
    for (int mt = 0; mt < MT; ++mt)
        #pragma unroll
        for (int nt = 0; nt < NT; ++nt)
            #pragma unroll
            for (int q = 0; q < 4; ++q) acc[mt][nt][q] = 0.f;

    // ldmatrix lane decomposition
    const int r_in = lane & 7;
    const int gA_m = ((lane >> 3) & 1) * 8;   // A: row offset within m16
    const int gA_u = (lane >> 4);             // A: 16B-unit offset (k8 group)
    const int gB_n = (lane >> 4) * 8;         // B: row offset within n16
    const int gB_u = ((lane >> 3) & 1);       // B: unit offset

    for (int it = 0; it < niter; ++it) {
        const int s = it % STAGES;
        MBARRIER_WAIT_PARITY(FULLB + s * 8, (it / STAGES) & 1);

        if (tid == 0) {
            int nx = it + STAGES - 1;
            if (nx < niter) {
                int sx = nx % STAGES;
                MBARRIER_EXPECT_TX(FULLB + sx * 8, STAGE_B);
                #pragma unroll
                for (int j = 0; j < NA; ++j)
                    TMA_LOAD_2D(TILE + sx * STAGE_B + j * 16384, &tmA,
                                nx * 64, m0 + j * 128, FULLB + sx * 8);
                #pragma unroll
                for (int j = 0; j < NB; ++j)
                    TMA_LOAD_2D(TILE + sx * STAGE_B + A_BYTES + j * 16384, &tmB,
                                nx * 64, n0 + j * 128, FULLB + sx * 8);
            }
        }

        const uint32_t As = TILE + s * STAGE_B;
        const uint32_t Bs = As + A_BYTES;

        #pragma unroll
        for (int kc = 0; kc < 4; ++kc) {
            uint32_t af[MT][4];
            #pragma unroll
            for (int mt = 0; mt < MT; ++mt) {
                int m = warp_m * (MT * 16) + mt * 16 + gA_m + r_in;
                int u = kc * 2 + gA_u;
                LDMATRIX_X4(af[mt][0], af[mt][1], af[mt][2], af[mt][3],
                            As + m * 128 + ((u ^ (m & 7)) << 4));
            }
            uint32_t bf[NT][2];
            #pragma unroll
            for (int nt2 = 0; nt2 < NT / 2; ++nt2) {
                int n = warp_n * (NT * 8) + nt2 * 16 + gB_n + r_in;
                int u = kc * 2 + gB_u;
                LDMATRIX_X4(bf[2*nt2][0], bf[2*nt2][1], bf[2*nt2+1][0], bf[2*nt2+1][1],
                            Bs + n * 128 + ((u ^ (n & 7)) << 4));
            }
            #pragma unroll
            for (int mt = 0; mt < MT; ++mt)
                #pragma unroll
                for (int nt = 0; nt < NT; ++nt)
                    mma_f16(acc[mt][nt], af[mt], bf[nt][0], bf[nt][1]);
        }
        __syncthreads();
    }

    // Epilogue: bias + activation (+ Qsum), fp16 half2 stores
    float qs = 0.f;
    const int r_lo = lane >> 2;
    const int c_lo = lane & 3;
    #pragma unroll
    for (int nt = 0; nt < NT; ++nt) {
        const int col = n0 + warp_n * (NT * 8) + nt * 8 + c_lo * 2;
        const float bias0 = bias[col], bias1 = bias[col + 1];
        #pragma unroll
        for (int mt = 0; mt < MT; ++mt) {
            const int row0 = m0 + warp_m * (MT * 16) + mt * 16 + r_lo;
            float v0 = acc[mt][nt][0] + bias0;
            float v1 = acc[mt][nt][1] + bias1;
            float v2 = acc[mt][nt][2] + bias0;
            float v3 = acc[mt][nt][3] + bias1;
            if (RELU) {
                v0 = fmaxf(v0, 0.f); v1 = fmaxf(v1, 0.f);
                v2 = fmaxf(v2, 0.f); v3 = fmaxf(v3, 0.f);
            }
            if (QSUM) qs += v0 * v0 + v1 * v1 + v2 * v2 + v3 * v3;
            *(__half2*)(C + (size_t)row0 * Nglob + col)       = __floats2half2_rn(v0, v1);
            *(__half2*)(C + (size_t)(row0 + 8) * Nglob + col) = __floats2half2_rn(v2, v3);
        }
    }
    if (QSUM) {
        qs = warp_sum(qs);
        if (lane == 0) atomicAdd(Qacc, qs);
    }
}

// ---------------------------------------------------------------------------
// Weight transpose to fp16 K-major: Wt[n*K + k] = half(W[k*N + n])
// ---------------------------------------------------------------------------
__global__ void transpose_kernel(const float* __restrict__ W, __half* __restrict__ Wt,
                                 int K, int N)
{
    __shared__ float t[32][33];
    int k0 = blockIdx.x * 32, n0 = blockIdx.y * 32;
    int x = threadIdx.x, y0 = threadIdx.y;
    #pragma unroll
    for (int dy = 0; dy < 32; dy += 8) {
        int k = k0 + y0 + dy, n = n0 + x;
        if (k < K && n < N) t[y0 + dy][x] = W[(size_t)k * N + n];
    }
    __syncthreads();
    #pragma unroll
    for (int dy = 0; dy < 32; dy += 8) {
        int n = n0 + y0 + dy, k = k0 + x;
        if (n < N && k < K) Wt[(size_t)n * K + k] = __float2half_rn(t[x][y0 + dy]);
    }
}

// ---------------------------------------------------------------------------
// Init / step / finalize
// ---------------------------------------------------------------------------
__global__ void init_kernel(const float* __restrict__ noisy) {
    long i = blockIdx.x * (long)blockDim.x + threadIdx.x;
    if (i < Tv) { g_res[i] = 0.f; g_del[i] = 0.f; g_Q[i] = 0.f; }
    if (i < (long)Bv * Cv) {
        int b = (int)(i / Cv), c = (int)(i - (long)b * Cv);
        float v = (c < 64) ? noisy[b * 64 + c] : 0.f;
        float* row = g_inp + (size_t)b * INFv;
        row[c] = v; row[Cv + c] = v; row[2*Cv + c] = v; row[3*Cv + c] = v;
    }
}

__global__ void step_kernel(int n) {
    __shared__ float sred[16];
    int i = blockIdx.x * blockDim.x + threadIdx.x;
    int b = i / Cv, c = i - b * Cv;
    float* row = g_inp + (size_t)b * INFv;
    float x = row[c], p = row[Cv + c], y = row[2*Cv + c], z = row[3*Cv + c];

    float u = 0.f, v = 0.f;
    if (n > 0) {
        // alpha(n) recomputed per-thread from prev iteration's reductions
        float delta  = g_del[n - 1];
        float Q      = 1.5f * g_Q[n - 1] + 1e-12f;
        float al = sqrtf(fminf(0.99f * fmaxf(delta, 0.f) / Q, 1.f));
        const __half* orow = g_devh + (size_t)b * OUTFv;
        u = al * __half2float(orow[c]);
        v = al * __half2float(orow[Cv + c]);
    }
    float nf = (float)n;
    float a  = nf / (nf + 3.f);

    float yn = x + a * (y - x) + u;
    float zp = a * (z - p);
    float zn = x + a * (p - x) + zp + u + v;
    float zm = zn - yn;
    float pr = copysignf(fmaxf(fabsf(zm) - 0.1f, 0.f), zm);
    float xn = x + (pr - zn) + zp;

    row[c] = xn; row[Cv + c] = pr; row[2*Cv + c] = yn; row[3*Cv + c] = zn;
    __half* hrow = g_inph + (size_t)b * INFv;
    hrow[c]        = __float2half_rn(xn);
    hrow[Cv + c]   = __float2half_rn(pr);
    hrow[2*Cv + c] = __float2half_rn(yn);
    hrow[3*Cv + c] = __float2half_rn(zn);

    float r = pr - yn; r *= r;
    float d = xn - zn; d *= d;
    r = warp_sum(r); d = warp_sum(d);
    int lane = threadIdx.x & 31, wid = threadIdx.x >> 5;
    if (lane == 0) { sred[wid] = r; sred[8 + wid] = d; }
    __syncthreads();
    if (wid == 0) {
        float rr = (lane < 8) ? sred[lane] : 0.f;
        rr = warp_sum(rr);
        if (lane == 0) atomicAdd(&g_res[n], rr);
    } else if (wid == 1) {
        float dd = (lane < 8) ? sred[8 + lane] : 0.f;
        dd = warp_sum(dd);
        if (lane == 0) atomicAdd(&g_del[n], dd);
    }
}

__global__ void finalize_kernel(float* __restrict__ out) {
    long i = blockIdx.x * (long)blockDim.x + threadIdx.x;
    if (i < (long)Bv * Cv) {
        int b = (int)(i / Cv), c = (int)(i - (long)b * Cv);
        out[i] = g_inp[(size_t)b * INFv + Cv + c];
    }
    if (i < Tv) out[(long)Bv * Cv + i] = sqrtf(g_res[i] + 1e-12f);
}

// ---------------------------------------------------------------------------
// Host side
// ---------------------------------------------------------------------------
typedef CUresult (*EncodeFn)(CUtensorMap*, CUtensorMapDataType, cuuint32_t, void*,
                             const cuuint64_t*, const cuuint64_t*, const cuuint32_t*,
                             const cuuint32_t*, CUtensorMapInterleave, CUtensorMapSwizzle,
                             CUtensorMapL2promotion, CUtensorMapFloatOOBfill);

static void make_map_h(EncodeFn enc, CUtensorMap* tm, void* base, int Kdim, int rows) {
    cuuint64_t dims[2]    = {(cuuint64_t)Kdim, (cuuint64_t)rows};
    cuuint64_t strides[1] = {(cuuint64_t)Kdim * 2};
    cuuint32_t box[2]     = {64u, 128u};
    cuuint32_t es[2]      = {1u, 1u};
    enc(tm, CU_TENSOR_MAP_DATA_TYPE_FLOAT16, 2, base, dims, strides, box, es,
        CU_TENSOR_MAP_INTERLEAVE_NONE, CU_TENSOR_MAP_SWIZZLE_128B,
        CU_TENSOR_MAP_L2_PROMOTION_L2_128B, CU_TENSOR_MAP_FLOAT_OOB_FILL_NONE);
}

extern "C" void kernel_launch(void* const* d_in, const int* in_sizes, int n_in,
                              void* d_out, int out_size) {
    const float* noisy = (const float*)d_in[0];
    const float* W1 = (const float*)d_in[1];
    const float* b1 = (const float*)d_in[2];
    const float* W2 = (const float*)d_in[3];
    const float* b2 = (const float*)d_in[4];
    const float* W3 = (const float*)d_in[5];
    const float* b3 = (const float*)d_in[6];
    float* out = (float*)d_out;

    __half *inph, *h1h, *h2h, *devh, *W1h, *W2h, *W3h;
    float *Qarr;
    cudaGetSymbolAddress((void**)&inph, g_inph);
    cudaGetSymbolAddress((void**)&h1h,  g_h1h);
    cudaGetSymbolAddress((void**)&h2h,  g_h2h);
    cudaGetSymbolAddress((void**)&devh, g_devh);
    cudaGetSymbolAddress((void**)&Qarr, g_Q);
    cudaGetSymbolAddress((void**)&W1h,  g_W1h);
    cudaGetSymbolAddress((void**)&W2h,  g_W2h);
    cudaGetSymbolAddress((void**)&W3h,  g_W3h);

    static EncodeFn enc = nullptr;
    if (!enc) {
        void* p = nullptr;
        cudaDriverEntryPointQueryResult st;
        cudaGetDriverEntryPoint("cuTensorMapEncodeTiled", &p, cudaEnableDefault, &st);
        enc = (EncodeFn)p;
    }

    CUtensorMap tA1, tB1, tA2, tB2, tA3, tB3;
    make_map_h(enc, &tA1, inph, INFv, Bv);
    make_map_h(enc, &tB1, W1h,  INFv, HIDv);
    make_map_h(enc, &tA2, h1h,  HIDv, Bv);
    make_map_h(enc, &tB2, W2h,  HIDv, HIDv);
    make_map_h(enc, &tA3, h2h,  HIDv, Bv);
    make_map_h(enc, &tB3, W3h,  HIDv, OUTFv);

    // smem: GEMM1/2 (MT=2,NT=8): (16+32)KB * 4 stages; GEMM3 (MT=4,NT=4): (32+16)KB * 4
    const int SMEM_SZ = 1024 + 4 * (3 * 16384);   // 197632
    static bool attr_set = false;
    if (!attr_set) {
        cudaFuncSetAttribute(hgemm<2,8,4,true ,false>, cudaFuncAttributeMaxDynamicSharedMemorySize, SMEM_SZ);
        cudaFuncSetAttribute(hgemm<4,4,4,false,true >, cudaFuncAttributeMaxDynamicSharedMemorySize, SMEM_SZ);
        attr_set = true;
    }

    dim3 tb(32, 8);
    transpose_kernel<<<dim3(INFv/32, HIDv/32),  tb>>>(W1, W1h, INFv, HIDv);
    transpose_kernel<<<dim3(HIDv/32, HIDv/32),  tb>>>(W2, W2h, HIDv, HIDv);
    transpose_kernel<<<dim3(HIDv/32, OUTFv/32), tb>>>(W3, W3h, HIDv, OUTFv);

    const int NBLK = (Bv * Cv) / 256;
    init_kernel<<<NBLK, 256>>>(noisy);

    dim3 g12(1, Bv / 128);           // CTA 128x256, grid (1,128)
    dim3 g3 (OUTFv / 128, Bv / 256); // CTA 256x128, grid (9,64)

    for (int n = 0; n < Tv; ++n) {
        step_kernel<<<NBLK, 256>>>(n);
        hgemm<2,8,4,true ,false><<<g12, 512, SMEM_SZ>>>(tA1, tB1, b1, h1h,  HIDv,  INFv, nullptr);
        hgemm<2,8,4,true ,false><<<g12, 512, SMEM_SZ>>>(tA2, tB2, b2, h2h,  HIDv,  HIDv, nullptr);
        hgemm<4,4,4,false,true ><<<g3,  512, SMEM_SZ>>>(tA3, tB3, b3, devh, OUTFv, HIDv, Qarr + n);
    }
    finalize_kernel<<<NBLK, 256>>>(out);
}

// round 5
// speedup vs baseline: 5.1538x; 1.1934x over previous
#include <cuda_runtime.h>
#include <cuda.h>
#include <cuda_fp16.h>
#include <math.h>
#include <stdint.h>

// Problem constants (fixed by setup_inputs)
#define Bv    16384
#define Cv    576          // N_CH*SIZE*SIZE
#define INFv  2304         // 4*Cv
#define HIDv  256
#define OUTFv 1152         // 2*Cv
#define Tv    20

// Persistent scratch (device globals; no allocations allowed)
__device__ __align__(1024) float  g_inp [(size_t)Bv * INFv];   // fp32 state [x|p|y|z]
__device__ __align__(1024) __half g_inph[(size_t)Bv * INFv];   // fp16 state copy (GEMM1 A)
__device__ __align__(1024) __half g_h2h [(size_t)Bv * HIDv];
__device__ __align__(1024) __half g_devh[(size_t)Bv * OUTFv];  // [u_raw | v_raw] fp16
__device__ __align__(1024) __half g_W1h[(size_t)HIDv  * INFv]; // K-major [256,2304]
__device__ __align__(1024) __half g_W2h[(size_t)HIDv  * HIDv];
__device__ __align__(1024) __half g_W3h[(size_t)OUTFv * HIDv];
__device__ float g_res[Tv];
__device__ float g_del[Tv];
__device__ float g_Q  [Tv];

// ---------------------------------------------------------------------------
// PTX helpers
// ---------------------------------------------------------------------------
__device__ __forceinline__ uint32_t smem_to_u32(const void* p) {
    uint32_t a;
    asm("{ .reg .u64 t; cvta.to.shared.u64 t, %1; cvt.u32.u64 %0, t; }"
        : "=r"(a) : "l"(p));
    return a;
}

#define MBARRIER_INIT(addr, cnt) \
    asm volatile("mbarrier.init.shared.b64 [%0], %1;" :: "r"((uint32_t)(addr)), "r"((uint32_t)(cnt)) : "memory")
#define MBARRIER_EXPECT_TX(addr, bytes) \
    asm volatile("mbarrier.arrive.expect_tx.shared.b64 _, [%0], %1;" :: "r"((uint32_t)(addr)), "r"((uint32_t)(bytes)) : "memory")

#define MBARRIER_WAIT_PARITY(mbar, par) do { \
    uint32_t _m = (uint32_t)(mbar), _p = (uint32_t)(par), _d; \
    asm volatile("{\n\t.reg .pred p;\n\t" \
        "mbarrier.try_wait.parity.acquire.cta.shared::cta.b64 p, [%1], %2;\n\t" \
        "selp.b32 %0, 1, 0, p;\n\t}" : "=r"(_d) : "r"(_m), "r"(_p) : "memory"); \
    if (!_d) { \
        asm volatile("{\n\t.reg .pred P1;\n\t" \
            "W_%=:\n\t" \
            "mbarrier.try_wait.parity.acquire.cta.shared::cta.b64 P1, [%0], %1, 0x989680;\n\t" \
            "@P1 bra.uni D_%=;\n\tbra.uni W_%=;\n\tD_%=:\n\t}" \
            :: "r"(_m), "r"(_p) : "memory"); \
    } \
} while(0)

#define TMA_LOAD_2D(smem_addr, map_ptr, cx, cy, mbar) \
    asm volatile("cp.async.bulk.tensor.2d.shared::cta.global.tile.mbarrier::complete_tx::bytes " \
        "[%0], [%1, {%2, %3}], [%4];" \
        :: "r"((uint32_t)(smem_addr)), "l"(map_ptr), "r"((int32_t)(cx)), "r"((int32_t)(cy)), \
           "r"((uint32_t)(mbar)) : "memory")

#define FENCE_PROXY_ASYNC() asm volatile("fence.proxy.async.shared::cta;" ::: "memory")

#define LDMATRIX_X4(r0, r1, r2, r3, addr) \
    asm volatile("ldmatrix.sync.aligned.m8n8.x4.shared.b16 {%0,%1,%2,%3}, [%4];" \
        : "=r"(r0), "=r"(r1), "=r"(r2), "=r"(r3) : "r"(addr))

__device__ __forceinline__ void mma_f16(float* d, const uint32_t* a,
                                        uint32_t b0, uint32_t b1) {
    asm volatile(
        "mma.sync.aligned.m16n8k16.row.col.f32.f16.f16.f32 "
        "{%0,%1,%2,%3}, {%4,%5,%6,%7}, {%8,%9}, {%0,%1,%2,%3};"
        : "+f"(d[0]), "+f"(d[1]), "+f"(d[2]), "+f"(d[3])
        : "r"(a[0]), "r"(a[1]), "r"(a[2]), "r"(a[3]), "r"(b0), "r"(b1));
}

__device__ __forceinline__ float warp_sum(float v) {
    #pragma unroll
    for (int o = 16; o > 0; o >>= 1) v += __shfl_down_sync(0xffffffffu, v, o);
    return v;
}

// ---------------------------------------------------------------------------
// FUSED GEMM1+GEMM2: one CTA owns 128 rows and the full N=256.
// Phase 1: h1 = relu(A[128,2304] @ W1t^T + b1)  (TMA pipeline, 4 stages)
//          -> h1 kept in SMEM (4 chunk tiles of [128x64] fp16, SW128)
// Phase 2: h2 = relu(h1 @ W2t^T + b2), W2 TMA-prefetched into dead slots
// ---------------------------------------------------------------------------
__global__ void __launch_bounds__(512, 1)
fused12(const __grid_constant__ CUtensorMap tmA,
        const __grid_constant__ CUtensorMap tmB1,
        const __grid_constant__ CUtensorMap tmB2,
        const float* __restrict__ b1, const float* __restrict__ b2,
        __half* __restrict__ h2out)
{
    constexpr int STAGES  = 4;
    constexpr int A_BYTES = 128 * 64 * 2;     // 16KB
    constexpr int B_BYTES = 256 * 64 * 2;     // 32KB
    constexpr int STAGE_B = A_BYTES + B_BYTES;
    constexpr int NITER   = INFv / 64;        // 36

    extern __shared__ char smem[];
    const uint32_t sb = smem_to_u32(smem);
    const int tid  = threadIdx.x;
    const int wid  = tid >> 5;
    const int lane = tid & 31;
    const int warp_m = wid >> 2;              // 0..3
    const int warp_n = wid & 3;               // 0..3
    const int m0 = blockIdx.x * 128;

    const uint32_t FULLB = sb;                // 8 mbarriers
    const uint32_t TILE  = sb + 1024;
    const uint32_t W2S   = TILE + 65536;      // W2 chunks: 4 x 32KB

    if (tid == 0) {
        #pragma unroll
        for (int s = 0; s < 8; ++s) MBARRIER_INIT(FULLB + s * 8, 1);
        FENCE_PROXY_ASYNC();
    }
    __syncthreads();

    if (tid == 0) {
        #pragma unroll
        for (int s = 0; s < STAGES - 1; ++s) {
            MBARRIER_EXPECT_TX(FULLB + s * 8, STAGE_B);
            TMA_LOAD_2D(TILE + s * STAGE_B, &tmA, s * 64, m0, FULLB + s * 8);
            TMA_LOAD_2D(TILE + s * STAGE_B + A_BYTES,         &tmB1, s * 64, 0,   FULLB + s * 8);
            TMA_LOAD_2D(TILE + s * STAGE_B + A_BYTES + 16384, &tmB1, s * 64, 128, FULLB + s * 8);
        }
    }

    float acc[2][8][4];
    #pragma unroll
    for (int mt = 0; mt < 2; ++mt)
        #pragma unroll
        for (int nt = 0; nt < 8; ++nt)
            #pragma unroll
            for (int q = 0; q < 4; ++q) acc[mt][nt][q] = 0.f;

    const int r_in = lane & 7;
    const int gA_m = ((lane >> 3) & 1) * 8;
    const int gA_u = (lane >> 4);
    const int gB_n = (lane >> 4) * 8;
    const int gB_u = ((lane >> 3) & 1);

    // ---- Phase 1 mainloop ----
    for (int it = 0; it < NITER; ++it) {
        const int s = it % STAGES;
        MBARRIER_WAIT_PARITY(FULLB + s * 8, (it / STAGES) & 1);

        if (tid == 0) {
            int nx = it + STAGES - 1;
            if (nx < NITER) {
                int sx = nx % STAGES;
                MBARRIER_EXPECT_TX(FULLB + sx * 8, STAGE_B);
                TMA_LOAD_2D(TILE + sx * STAGE_B, &tmA, nx * 64, m0, FULLB + sx * 8);
                TMA_LOAD_2D(TILE + sx * STAGE_B + A_BYTES,         &tmB1, nx * 64, 0,   FULLB + sx * 8);
                TMA_LOAD_2D(TILE + sx * STAGE_B + A_BYTES + 16384, &tmB1, nx * 64, 128, FULLB + sx * 8);
            }
        }

        const uint32_t As = TILE + s * STAGE_B;
        const uint32_t Bs = As + A_BYTES;

        #pragma unroll
        for (int kc = 0; kc < 4; ++kc) {
            uint32_t af[2][4];
            #pragma unroll
            for (int mt = 0; mt < 2; ++mt) {
                int m = warp_m * 32 + mt * 16 + gA_m + r_in;
                int u = kc * 2 + gA_u;
                LDMATRIX_X4(af[mt][0], af[mt][1], af[mt][2], af[mt][3],
                            As + m * 128 + ((u ^ (m & 7)) << 4));
            }
            uint32_t bf[8][2];
            #pragma unroll
            for (int nt2 = 0; nt2 < 4; ++nt2) {
                int n = warp_n * 64 + nt2 * 16 + gB_n + r_in;
                int u = kc * 2 + gB_u;
                LDMATRIX_X4(bf[2*nt2][0], bf[2*nt2][1], bf[2*nt2+1][0], bf[2*nt2+1][1],
                            Bs + n * 128 + ((u ^ (n & 7)) << 4));
            }
            #pragma unroll
            for (int mt = 0; mt < 2; ++mt)
                #pragma unroll
                for (int nt = 0; nt < 8; ++nt)
                    mma_f16(acc[mt][nt], af[mt], bf[nt][0], bf[nt][1]);
        }
        __syncthreads();
    }

    // ---- Prefetch W2 into freed slots; write h1 into SMEM (chunk format) ----
    if (tid == 0) {
        #pragma unroll
        for (int kc2 = 0; kc2 < 4; ++kc2) {
            MBARRIER_EXPECT_TX(FULLB + (4 + kc2) * 8, 32768);
            TMA_LOAD_2D(W2S + kc2 * 32768,         &tmB2, kc2 * 64, 0,   FULLB + (4 + kc2) * 8);
            TMA_LOAD_2D(W2S + kc2 * 32768 + 16384, &tmB2, kc2 * 64, 128, FULLB + (4 + kc2) * 8);
        }
    }

    {
        const int r_lo = lane >> 2;
        const int c_lo = lane & 3;
        #pragma unroll
        for (int nt = 0; nt < 8; ++nt) {
            const int col = warp_n * 64 + nt * 8 + c_lo * 2;
            const float bias0 = b1[col], bias1 = b1[col + 1];
            #pragma unroll
            for (int mt = 0; mt < 2; ++mt) {
                const int mrow0 = warp_m * 32 + mt * 16 + r_lo;   // CTA-local row
                float v0 = fmaxf(acc[mt][nt][0] + bias0, 0.f);
                float v1 = fmaxf(acc[mt][nt][1] + bias1, 0.f);
                float v2 = fmaxf(acc[mt][nt][2] + bias0, 0.f);
                float v3 = fmaxf(acc[mt][nt][3] + bias1, 0.f);
                __half2 h01 = __floats2half2_rn(v0, v1);
                __half2 h23 = __floats2half2_rn(v2, v3);
                // h1 chunk = warp_n, 16B unit = nt, within-unit byte = c_lo*4
                char* base = smem + 1024 + warp_n * 16384;
                *(__half2*)(base + mrow0 * 128 + ((nt ^ (mrow0 & 7)) << 4) + c_lo * 4) = h01;
                int mrow1 = mrow0 + 8;
                *(__half2*)(base + mrow1 * 128 + ((nt ^ (mrow1 & 7)) << 4) + c_lo * 4) = h23;
            }
        }
    }
    #pragma unroll
    for (int mt = 0; mt < 2; ++mt)
        #pragma unroll
        for (int nt = 0; nt < 8; ++nt)
            #pragma unroll
            for (int q = 0; q < 4; ++q) acc[mt][nt][q] = 0.f;
    __syncthreads();

    // ---- Phase 2: h2 = relu(h1 @ W2^T + b2), K=256 in 4 chunks ----
    #pragma unroll
    for (int kc2 = 0; kc2 < 4; ++kc2) {
        MBARRIER_WAIT_PARITY(FULLB + (4 + kc2) * 8, 0);
        const uint32_t As2 = TILE + kc2 * 16384;
        const uint32_t Bs2 = W2S  + kc2 * 32768;
        #pragma unroll
        for (int kc = 0; kc < 4; ++kc) {
            uint32_t af[2][4];
            #pragma unroll
            for (int mt = 0; mt < 2; ++mt) {
                int m = warp_m * 32 + mt * 16 + gA_m + r_in;
                int u = kc * 2 + gA_u;
                LDMATRIX_X4(af[mt][0], af[mt][1], af[mt][2], af[mt][3],
                            As2 + m * 128 + ((u ^ (m & 7)) << 4));
            }
            uint32_t bf[8][2];
            #pragma unroll
            for (int nt2 = 0; nt2 < 4; ++nt2) {
                int n = warp_n * 64 + nt2 * 16 + gB_n + r_in;
                int u = kc * 2 + gB_u;
                LDMATRIX_X4(bf[2*nt2][0], bf[2*nt2][1], bf[2*nt2+1][0], bf[2*nt2+1][1],
                            Bs2 + n * 128 + ((u ^ (n & 7)) << 4));
            }
            #pragma unroll
            for (int mt = 0; mt < 2; ++mt)
                #pragma unroll
                for (int nt = 0; nt < 8; ++nt)
                    mma_f16(acc[mt][nt], af[mt], bf[nt][0], bf[nt][1]);
        }
    }

    // ---- Phase 2 epilogue: h2 -> gmem fp16 ----
    {
        const int r_lo = lane >> 2;
        const int c_lo = lane & 3;
        #pragma unroll
        for (int nt = 0; nt < 8; ++nt) {
            const int col = warp_n * 64 + nt * 8 + c_lo * 2;
            const float bias0 = b2[col], bias1 = b2[col + 1];
            #pragma unroll
            for (int mt = 0; mt < 2; ++mt) {
                const int row0 = m0 + warp_m * 32 + mt * 16 + r_lo;
                float v0 = fmaxf(acc[mt][nt][0] + bias0, 0.f);
                float v1 = fmaxf(acc[mt][nt][1] + bias1, 0.f);
                float v2 = fmaxf(acc[mt][nt][2] + bias0, 0.f);
                float v3 = fmaxf(acc[mt][nt][3] + bias1, 0.f);
                *(__half2*)(h2out + (size_t)row0 * HIDv + col)       = __floats2half2_rn(v0, v1);
                *(__half2*)(h2out + (size_t)(row0 + 8) * HIDv + col) = __floats2half2_rn(v2, v3);
            }
        }
    }
}

// ---------------------------------------------------------------------------
// fp16 mma.sync GEMM (GEMM3): dev = h2 @ W3t^T + b3, Qsum
// CTA (MT*64) x (NT*32), 512 threads, TMA pipeline (unchanged from R4)
// ---------------------------------------------------------------------------
template<int MT, int NT, int STAGES, bool RELU, bool QSUM>
__global__ void __launch_bounds__(512, 1)
hgemm(const __grid_constant__ CUtensorMap tmA,
      const __grid_constant__ CUtensorMap tmB,
      const float* __restrict__ bias, __half* __restrict__ C,
      int Nglob, int K, float* __restrict__ Qacc)
{
    constexpr int CTA_M   = MT * 64;
    constexpr int CTA_N   = NT * 32;
    constexpr int NA      = CTA_M / 128;
    constexpr int NB      = CTA_N / 128;
    constexpr int A_BYTES = CTA_M * 64 * 2;
    constexpr int B_BYTES = CTA_N * 64 * 2;
    constexpr int STAGE_B = A_BYTES + B_BYTES;

    extern __shared__ char smem[];
    const uint32_t sb = smem_to_u32(smem);
    const int tid  = threadIdx.x;
    const int wid  = tid >> 5;
    const int lane = tid & 31;
    const int warp_m = wid >> 2;
    const int warp_n = wid & 3;
    const int m0 = blockIdx.y * CTA_M;
    const int n0 = blockIdx.x * CTA_N;
    const int niter = K / 64;

    const uint32_t FULLB = sb;
    const uint32_t TILE  = sb + 1024;

    if (tid == 0) {
        #pragma unroll
        for (int s = 0; s < STAGES; ++s) MBARRIER_INIT(FULLB + s * 8, 1);
        FENCE_PROXY_ASYNC();
    }
    __syncthreads();

    if (tid == 0) {
        #pragma unroll
        for (int s = 0; s < STAGES - 1; ++s) {
            if (s < niter) {
                MBARRIER_EXPECT_TX(FULLB + s * 8, STAGE_B);
                #pragma unroll
                for (int j = 0; j < NA; ++j)
                    TMA_LOAD_2D(TILE + s * STAGE_B + j * 16384, &tmA,
                                s * 64, m0 + j * 128, FULLB + s * 8);
                #pragma unroll
                for (int j = 0; j < NB; ++j)
                    TMA_LOAD_2D(TILE + s * STAGE_B + A_BYTES + j * 16384, &tmB,
                                s * 64, n0 + j * 128, FULLB + s * 8);
            }
        }
    }

    float acc[MT][NT][4];
    #pragma unroll
    for (int mt = 0; mt < MT; ++mt)
        #pragma unroll
        for (int nt = 0; nt < NT; ++nt)
            #pragma unroll
            for (int q = 0; q < 4; ++q) acc[mt][nt][q] = 0.f;

    const int r_in = lane & 7;
    const int gA_m = ((lane >> 3) & 1) * 8;
    const int gA_u = (lane >> 4);
    const int gB_n = (lane >> 4) * 8;
    const int gB_u = ((lane >> 3) & 1);

    for (int it = 0; it < niter; ++it) {
        const int s = it % STAGES;
        MBARRIER_WAIT_PARITY(FULLB + s * 8, (it / STAGES) & 1);

        if (tid == 0) {
            int nx = it + STAGES - 1;
            if (nx < niter) {
                int sx = nx % STAGES;
                MBARRIER_EXPECT_TX(FULLB + sx * 8, STAGE_B);
                #pragma unroll
                for (int j = 0; j < NA; ++j)
                    TMA_LOAD_2D(TILE + sx * STAGE_B + j * 16384, &tmA,
                                nx * 64, m0 + j * 128, FULLB + sx * 8);
                #pragma unroll
                for (int j = 0; j < NB; ++j)
                    TMA_LOAD_2D(TILE + sx * STAGE_B + A_BYTES + j * 16384, &tmB,
                                nx * 64, n0 + j * 128, FULLB + sx * 8);
            }
        }

        const uint32_t As = TILE + s * STAGE_B;
        const uint32_t Bs = As + A_BYTES;

        #pragma unroll
        for (int kc = 0; kc < 4; ++kc) {
            uint32_t af[MT][4];
            #pragma unroll
            for (int mt = 0; mt < MT; ++mt) {
                int m = warp_m * (MT * 16) + mt * 16 + gA_m + r_in;
                int u = kc * 2 + gA_u;
                LDMATRIX_X4(af[mt][0], af[mt][1], af[mt][2], af[mt][3],
                            As + m * 128 + ((u ^ (m & 7)) << 4));
            }
            uint32_t bf[NT][2];
            #pragma unroll
            for (int nt2 = 0; nt2 < NT / 2; ++nt2) {
                int n = warp_n * (NT * 8) + nt2 * 16 + gB_n + r_in;
                int u = kc * 2 + gB_u;
                LDMATRIX_X4(bf[2*nt2][0], bf[2*nt2][1], bf[2*nt2+1][0], bf[2*nt2+1][1],
                            Bs + n * 128 + ((u ^ (n & 7)) << 4));
            }
            #pragma unroll
            for (int mt = 0; mt < MT; ++mt)
                #pragma unroll
                for (int nt = 0; nt < NT; ++nt)
                    mma_f16(acc[mt][nt], af[mt], bf[nt][0], bf[nt][1]);
        }
        __syncthreads();
    }

    float qs = 0.f;
    const int r_lo = lane >> 2;
    const int c_lo = lane & 3;
    #pragma unroll
    for (int nt = 0; nt < NT; ++nt) {
        const int col = n0 + warp_n * (NT * 8) + nt * 8 + c_lo * 2;
        const float bias0 = bias[col], bias1 = bias[col + 1];
        #pragma unroll
        for (int mt = 0; mt < MT; ++mt) {
            const int row0 = m0 + warp_m * (MT * 16) + mt * 16 + r_lo;
            float v0 = acc[mt][nt][0] + bias0;
            float v1 = acc[mt][nt][1] + bias1;
            float v2 = acc[mt][nt][2] + bias0;
            float v3 = acc[mt][nt][3] + bias1;
            if (RELU) {
                v0 = fmaxf(v0, 0.f); v1 = fmaxf(v1, 0.f);
                v2 = fmaxf(v2, 0.f); v3 = fmaxf(v3, 0.f);
            }
            if (QSUM) qs += v0 * v0 + v1 * v1 + v2 * v2 + v3 * v3;
            *(__half2*)(C + (size_t)row0 * Nglob + col)       = __floats2half2_rn(v0, v1);
            *(__half2*)(C + (size_t)(row0 + 8) * Nglob + col) = __floats2half2_rn(v2, v3);
        }
    }
    if (QSUM) {
        qs = warp_sum(qs);
        if (lane == 0) atomicAdd(Qacc, qs);
    }
}

// ---------------------------------------------------------------------------
// Weight transpose to fp16 K-major
// ---------------------------------------------------------------------------
__global__ void transpose_kernel(const float* __restrict__ W, __half* __restrict__ Wt,
                                 int K, int N)
{
    __shared__ float t[32][33];
    int k0 = blockIdx.x * 32, n0 = blockIdx.y * 32;
    int x = threadIdx.x, y0 = threadIdx.y;
    #pragma unroll
    for (int dy = 0; dy < 32; dy += 8) {
        int k = k0 + y0 + dy, n = n0 + x;
        if (k < K && n < N) t[y0 + dy][x] = W[(size_t)k * N + n];
    }
    __syncthreads();
    #pragma unroll
    for (int dy = 0; dy < 32; dy += 8) {
        int n = n0 + y0 + dy, k = k0 + x;
        if (n < N && k < K) Wt[(size_t)n * K + k] = __float2half_rn(t[x][y0 + dy]);
    }
}

// ---------------------------------------------------------------------------
// Vectorized init / step / finalize (float4 per thread, 512-thread blocks)
// grid = Bv*144/512 = 4608
// ---------------------------------------------------------------------------
__global__ void __launch_bounds__(512)
init_kernel(const float* __restrict__ noisy) {
    int i = blockIdx.x * 512 + threadIdx.x;       // vec4 index, total Bv*144
    if (i < Tv) { g_res[i] = 0.f; g_del[i] = 0.f; g_Q[i] = 0.f; }
    int b = i / 144, c4 = (i - b * 144) * 4;
    float4 v = make_float4(0.f, 0.f, 0.f, 0.f);
    if (c4 < 64) v = *(const float4*)(noisy + b * 64 + c4);
    float* row = g_inp + (size_t)b * INFv;
    *(float4*)(row + c4)          = v;
    *(float4*)(row + Cv + c4)     = v;
    *(float4*)(row + 2*Cv + c4)   = v;
    *(float4*)(row + 3*Cv + c4)   = v;
}

__global__ void __launch_bounds__(512)
step_kernel(int n) {
    __shared__ float sred[32];
    int i = blockIdx.x * 512 + threadIdx.x;
    int b = i / 144, c4 = (i - b * 144) * 4;
    float* row = g_inp + (size_t)b * INFv;
    float4 x = *(float4*)(row + c4);
    float4 p = *(float4*)(row + Cv + c4);
    float4 y = *(float4*)(row + 2*Cv + c4);
    float4 z = *(float4*)(row + 3*Cv + c4);

    float uu[4] = {0.f, 0.f, 0.f, 0.f}, vv[4] = {0.f, 0.f, 0.f, 0.f};
    if (n > 0) {
        float delta = g_del[n - 1];
        float Q     = 1.5f * g_Q[n - 1] + 1e-12f;
        float al = sqrtf(fminf(0.99f * fmaxf(delta, 0.f) / Q, 1.f));
        const __half* orow = g_devh + (size_t)b * OUTFv;
        uint2 ur = *(const uint2*)(orow + c4);
        uint2 vr = *(const uint2*)(orow + Cv + c4);
        __half2 u0 = *(__half2*)&ur.x, u1 = *(__half2*)&ur.y;
        __half2 w0 = *(__half2*)&vr.x, w1 = *(__half2*)&vr.y;
        uu[0] = al * __low2float(u0); uu[1] = al * __high2float(u0);
        uu[2] = al * __low2float(u1); uu[3] = al * __high2float(u1);
        vv[0] = al * __low2float(w0); vv[1] = al * __high2float(w0);
        vv[2] = al * __low2float(w1); vv[3] = al * __high2float(w1);
    }
    float nf = (float)n;
    float a  = nf / (nf + 3.f);

    float xs[4] = {x.x, x.y, x.z, x.w};
    float ps[4] = {p.x, p.y, p.z, p.w};
    float ys[4] = {y.x, y.y, y.z, y.w};
    float zs[4] = {z.x, z.y, z.z, z.w};
    float xn[4], pr[4], yn[4], zn[4];
    float rsum = 0.f, dsum = 0.f;
    #pragma unroll
    for (int j = 0; j < 4; ++j) {
        float ynj = xs[j] + a * (ys[j] - xs[j]) + uu[j];
        float zp  = a * (zs[j] - ps[j]);
        float znj = xs[j] + a * (ps[j] - xs[j]) + zp + uu[j] + vv[j];
        float zm  = znj - ynj;
        float prj = copysignf(fmaxf(fabsf(zm) - 0.1f, 0.f), zm);
        float xnj = xs[j] + (prj - znj) + zp;
        xn[j] = xnj; pr[j] = prj; yn[j] = ynj; zn[j] = znj;
        float r = prj - ynj; rsum += r * r;
        float d = xnj - znj; dsum += d * d;
    }
    *(float4*)(row + c4)        = make_float4(xn[0], xn[1], xn[2], xn[3]);
    *(float4*)(row + Cv + c4)   = make_float4(pr[0], pr[1], pr[2], pr[3]);
    *(float4*)(row + 2*Cv + c4) = make_float4(yn[0], yn[1], yn[2], yn[3]);
    *(float4*)(row + 3*Cv + c4) = make_float4(zn[0], zn[1], zn[2], zn[3]);

    __half* hrow = g_inph + (size_t)b * INFv;
    uint2 hx, hp, hy, hz;
    *(__half2*)&hx.x = __floats2half2_rn(xn[0], xn[1]);
    *(__half2*)&hx.y = __floats2half2_rn(xn[2], xn[3]);
    *(__half2*)&hp.x = __floats2half2_rn(pr[0], pr[1]);
    *(__half2*)&hp.y = __floats2half2_rn(pr[2], pr[3]);
    *(__half2*)&hy.x = __floats2half2_rn(yn[0], yn[1]);
    *(__half2*)&hy.y = __floats2half2_rn(yn[2], yn[3]);
    *(__half2*)&hz.x = __floats2half2_rn(zn[0], zn[1]);
    *(__half2*)&hz.y = __floats2half2_rn(zn[2], zn[3]);
    *(uint2*)(hrow + c4)        = hx;
    *(uint2*)(hrow + Cv + c4)   = hp;
    *(uint2*)(hrow + 2*Cv + c4) = hy;
    *(uint2*)(hrow + 3*Cv + c4) = hz;

    rsum = warp_sum(rsum); dsum = warp_sum(dsum);
    int lane = threadIdx.x & 31, wid = threadIdx.x >> 5;
    if (lane == 0) { sred[wid] = rsum; sred[16 + wid] = dsum; }
    __syncthreads();
    if (wid == 0) {
        float rr = (lane < 16) ? sred[lane] : 0.f;
        rr = warp_sum(rr);
        if (lane == 0) atomicAdd(&g_res[n], rr);
    } else if (wid == 1) {
        float dd = (lane < 16) ? sred[16 + lane] : 0.f;
        dd = warp_sum(dd);
        if (lane == 0) atomicAdd(&g_del[n], dd);
    }
}

__global__ void __launch_bounds__(512)
finalize_kernel(float* __restrict__ out) {
    int i = blockIdx.x * 512 + threadIdx.x;
    int b = i / 144, c4 = (i - b * 144) * 4;
    *(float4*)(out + (size_t)b * Cv + c4) = *(float4*)(g_inp + (size_t)b * INFv + Cv + c4);
    if (i < Tv) out[(size_t)Bv * Cv + i] = sqrtf(g_res[i] + 1e-12f);
}

// ---------------------------------------------------------------------------
// Host side
// ---------------------------------------------------------------------------
typedef CUresult (*EncodeFn)(CUtensorMap*, CUtensorMapDataType, cuuint32_t, void*,
                             const cuuint64_t*, const cuuint64_t*, const cuuint32_t*,
                             const cuuint32_t*, CUtensorMapInterleave, CUtensorMapSwizzle,
                             CUtensorMapL2promotion, CUtensorMapFloatOOBfill);

static void make_map_h(EncodeFn enc, CUtensorMap* tm, void* base, int Kdim, int rows) {
    cuuint64_t dims[2]    = {(cuuint64_t)Kdim, (cuuint64_t)rows};
    cuuint64_t strides[1] = {(cuuint64_t)Kdim * 2};
    cuuint32_t box[2]     = {64u, 128u};
    cuuint32_t es[2]      = {1u, 1u};
    enc(tm, CU_TENSOR_MAP_DATA_TYPE_FLOAT16, 2, base, dims, strides, box, es,
        CU_TENSOR_MAP_INTERLEAVE_NONE, CU_TENSOR_MAP_SWIZZLE_128B,
        CU_TENSOR_MAP_L2_PROMOTION_L2_128B, CU_TENSOR_MAP_FLOAT_OOB_FILL_NONE);
}

extern "C" void kernel_launch(void* const* d_in, const int* in_sizes, int n_in,
                              void* d_out, int out_size) {
    const float* noisy = (const float*)d_in[0];
    const float* W1 = (const float*)d_in[1];
    const float* b1 = (const float*)d_in[2];
    const float* W2 = (const float*)d_in[3];
    const float* b2 = (const float*)d_in[4];
    const float* W3 = (const float*)d_in[5];
    const float* b3 = (const float*)d_in[6];
    float* out = (float*)d_out;

    __half *inph, *h2h, *devh, *W1h, *W2h, *W3h;
    float *Qarr;
    cudaGetSymbolAddress((void**)&inph, g_inph);
    cudaGetSymbolAddress((void**)&h2h,  g_h2h);
    cudaGetSymbolAddress((void**)&devh, g_devh);
    cudaGetSymbolAddress((void**)&Qarr, g_Q);
    cudaGetSymbolAddress((void**)&W1h,  g_W1h);
    cudaGetSymbolAddress((void**)&W2h,  g_W2h);
    cudaGetSymbolAddress((void**)&W3h,  g_W3h);

    static EncodeFn enc = nullptr;
    if (!enc) {
        void* p = nullptr;
        cudaDriverEntryPointQueryResult st;
        cudaGetDriverEntryPoint("cuTensorMapEncodeTiled", &p, cudaEnableDefault, &st);
        enc = (EncodeFn)p;
    }

    CUtensorMap tA1, tB1, tB2, tA3, tB3;
    make_map_h(enc, &tA1, inph, INFv, Bv);
    make_map_h(enc, &tB1, W1h,  INFv, HIDv);
    make_map_h(enc, &tB2, W2h,  HIDv, HIDv);
    make_map_h(enc, &tA3, h2h,  HIDv, Bv);
    make_map_h(enc, &tB3, W3h,  HIDv, OUTFv);

    const int SMEM_SZ = 1024 + 4 * (3 * 16384);   // 197632
    static bool attr_set = false;
    if (!attr_set) {
        cudaFuncSetAttribute(fused12, cudaFuncAttributeMaxDynamicSharedMemorySize, SMEM_SZ);
        cudaFuncSetAttribute(hgemm<4,4,4,false,true>, cudaFuncAttributeMaxDynamicSharedMemorySize, SMEM_SZ);
        attr_set = true;
    }

    dim3 tb(32, 8);
    transpose_kernel<<<dim3(INFv/32, HIDv/32),  tb>>>(W1, W1h, INFv, HIDv);
    transpose_kernel<<<dim3(HIDv/32, HIDv/32),  tb>>>(W2, W2h, HIDv, HIDv);
    transpose_kernel<<<dim3(HIDv/32, OUTFv/32), tb>>>(W3, W3h, HIDv, OUTFv);

    const int VBLK = (Bv * 144) / 512;   // 4608
    init_kernel<<<VBLK, 512>>>(noisy);

    dim3 g3(OUTFv / 128, Bv / 256);      // (9, 64)

    for (int n = 0; n < Tv; ++n) {
        step_kernel<<<VBLK, 512>>>(n);
        fused12<<<Bv / 128, 512, SMEM_SZ>>>(tA1, tB1, tB2, b1, b2, h2h);
        hgemm<4,4,4,false,true><<<g3, 512, SMEM_SZ>>>(tA3, tB3, b3, devh, OUTFv, HIDv, Qarr + n);
    }
    finalize_kernel<<<VBLK, 512>>>(out);
}